// round 3
// baseline (speedup 1.0000x reference)
#include <cuda_runtime.h>

#define S_TOK     2304
#define D_MODEL   3072
#define NHEAD     24
#define HDIM      128
#define BLOCK_TOK 2048
#define CONDN     256
#define RANKN     128
#define T_IPN     128
#define D_IPN     4096
#define EPSV      1e-5f
// (1/sqrt(128)) * log2(e), so softmax exp -> exp2
#define QSCALE    0.1275173e+0f

// ---------------- device scratch ----------------
__device__ float g_q[S_TOK * D_MODEL];
__device__ float g_k[S_TOK * D_MODEL];
__device__ float g_v[S_TOK * D_MODEL];
__device__ float g_kip[T_IPN * D_MODEL];
__device__ float g_vip[T_IPN * D_MODEL];
__device__ float g_lt[3 * CONDN * RANKN];

// ---------------- helpers ----------------
__device__ __forceinline__ unsigned f2tf(float f) {
    unsigned u;
    asm("cvt.rna.tf32.f32 %0, %1;" : "=r"(u) : "f"(f));
    return u;
}

__device__ __forceinline__ void mma8(float* c, const unsigned* a, unsigned b0, unsigned b1) {
    asm volatile(
        "mma.sync.aligned.m16n8k8.row.col.f32.tf32.tf32.f32 "
        "{%0,%1,%2,%3}, {%4,%5,%6,%7}, {%8,%9}, {%0,%1,%2,%3};"
        : "+f"(c[0]), "+f"(c[1]), "+f"(c[2]), "+f"(c[3])
        : "r"(a[0]), "r"(a[1]), "r"(a[2]), "r"(a[3]), "r"(b0), "r"(b1));
}

// ================= GEMM (tf32 tensor): C[M,N] (+)= A[M,K] @ B[N,K]^T + bias =================
// 128x128 block tile, BK=16, 128 threads (4 warps), warp tile 64x64.
// Smem k-major [k][mn] stride 136 -> conflict-free frag LDS and transpose STS.
struct Gemm3 {
    const float* A[3];
    const float* B[3];
    const float* bias[3];
    float*       C[3];
};

template <bool ACC>
__global__ __launch_bounds__(128, 2) void gemm_tc(Gemm3 P, int K, int lda, int ldb, int ldc)
{
    __shared__ unsigned As[2][16 * 136];
    __shared__ unsigned Bs[2][16 * 136];

    const int z = blockIdx.z;
    const float* A    = P.A[z];
    const float* B    = P.B[z];
    const float* bias = P.bias[z];
    float*       C    = P.C[z];

    const int tid = threadIdx.x;
    const int l = tid & 31, w = tid >> 5;
    const int g = l >> 2, t = l & 3;
    const int wm = w & 1, wn = w >> 1;
    const int bm = blockIdx.y << 7, bn = blockIdx.x << 7;

    const float* Ar = A + (size_t)(bm + tid) * lda;
    const float* Br = B + (size_t)(bn + tid) * ldb;

    float c[4][8][4];
#pragma unroll
    for (int mt = 0; mt < 4; mt++)
#pragma unroll
        for (int nt = 0; nt < 8; nt++)
#pragma unroll
            for (int i = 0; i < 4; i++) c[mt][nt][i] = 0.f;

    float4 a4[4], b4[4];
#pragma unroll
    for (int i = 0; i < 4; i++) {
        a4[i] = *(const float4*)(Ar + i * 4);
        b4[i] = *(const float4*)(Br + i * 4);
    }
#pragma unroll
    for (int i = 0; i < 4; i++) {
        As[0][(i * 4 + 0) * 136 + tid] = f2tf(a4[i].x);
        As[0][(i * 4 + 1) * 136 + tid] = f2tf(a4[i].y);
        As[0][(i * 4 + 2) * 136 + tid] = f2tf(a4[i].z);
        As[0][(i * 4 + 3) * 136 + tid] = f2tf(a4[i].w);
        Bs[0][(i * 4 + 0) * 136 + tid] = f2tf(b4[i].x);
        Bs[0][(i * 4 + 1) * 136 + tid] = f2tf(b4[i].y);
        Bs[0][(i * 4 + 2) * 136 + tid] = f2tf(b4[i].z);
        Bs[0][(i * 4 + 3) * 136 + tid] = f2tf(b4[i].w);
    }
    __syncthreads();

    const int niter = K >> 4;
    for (int it = 0; it < niter; it++) {
        const int cur = it & 1;
        if (it + 1 < niter) {
            const int k0 = (it + 1) << 4;
#pragma unroll
            for (int i = 0; i < 4; i++) {
                a4[i] = *(const float4*)(Ar + k0 + i * 4);
                b4[i] = *(const float4*)(Br + k0 + i * 4);
            }
        }
#pragma unroll
        for (int ks = 0; ks < 2; ks++) {
            const int kr = ks * 8 + t;
            unsigned af[4][4], bf[8][2];
#pragma unroll
            for (int mt = 0; mt < 4; mt++) {
                const int m0 = wm * 64 + mt * 16;
                af[mt][0] = As[cur][kr * 136 + m0 + g];
                af[mt][1] = As[cur][kr * 136 + m0 + g + 8];
                af[mt][2] = As[cur][(kr + 4) * 136 + m0 + g];
                af[mt][3] = As[cur][(kr + 4) * 136 + m0 + g + 8];
            }
#pragma unroll
            for (int nt = 0; nt < 8; nt++) {
                const int n0 = wn * 64 + nt * 8;
                bf[nt][0] = Bs[cur][kr * 136 + n0 + g];
                bf[nt][1] = Bs[cur][(kr + 4) * 136 + n0 + g];
            }
#pragma unroll
            for (int mt = 0; mt < 4; mt++)
#pragma unroll
                for (int nt = 0; nt < 8; nt++)
                    mma8(c[mt][nt], af[mt], bf[nt][0], bf[nt][1]);
        }
        __syncthreads();
        if (it + 1 < niter) {
            const int nxt = cur ^ 1;
#pragma unroll
            for (int i = 0; i < 4; i++) {
                As[nxt][(i * 4 + 0) * 136 + tid] = f2tf(a4[i].x);
                As[nxt][(i * 4 + 1) * 136 + tid] = f2tf(a4[i].y);
                As[nxt][(i * 4 + 2) * 136 + tid] = f2tf(a4[i].z);
                As[nxt][(i * 4 + 3) * 136 + tid] = f2tf(a4[i].w);
                Bs[nxt][(i * 4 + 0) * 136 + tid] = f2tf(b4[i].x);
                Bs[nxt][(i * 4 + 1) * 136 + tid] = f2tf(b4[i].y);
                Bs[nxt][(i * 4 + 2) * 136 + tid] = f2tf(b4[i].z);
                Bs[nxt][(i * 4 + 3) * 136 + tid] = f2tf(b4[i].w);
            }
        }
        __syncthreads();
    }

    // epilogue
#pragma unroll
    for (int mt = 0; mt < 4; mt++) {
        const int r0 = bm + wm * 64 + mt * 16 + g;
        const int r1 = r0 + 8;
#pragma unroll
        for (int nt = 0; nt < 8; nt++) {
            const int cc = bn + wn * 64 + nt * 8 + 2 * t;
            float2 v0 = make_float2(c[mt][nt][0], c[mt][nt][1]);
            float2 v1 = make_float2(c[mt][nt][2], c[mt][nt][3]);
            if (bias) {
                float bx = bias[cc], by = bias[cc + 1];
                v0.x += bx; v0.y += by; v1.x += bx; v1.y += by;
            }
            float* p0 = C + (size_t)r0 * ldc + cc;
            float* p1 = C + (size_t)r1 * ldc + cc;
            if (ACC) {
                float2 e0 = *(const float2*)p0, e1 = *(const float2*)p1;
                v0.x += e0.x; v0.y += e0.y; v1.x += e1.x; v1.y += e1.y;
            }
            *(float2*)p0 = v0;
            *(float2*)p1 = v1;
        }
    }
}

// ---------------- rmsnorm (+weight) (+rope), one warp per (token, head) ----------------
__global__ void norm_rope_kernel(float* __restrict__ t, const float* __restrict__ w,
                                 const float* __restrict__ cs, const float* __restrict__ sn,
                                 int rows, int do_rope)
{
    int gwarp = (blockIdx.x * blockDim.x + threadIdx.x) >> 5;
    int lane = threadIdx.x & 31;
    if (gwarp >= rows * NHEAD) return;
    int s = gwarp / NHEAD, h = gwarp % NHEAD;
    float* p = t + (size_t)s * D_MODEL + h * HDIM + lane * 4;
    float4 x = *(const float4*)p;
    float ss = x.x * x.x + x.y * x.y + x.z * x.z + x.w * x.w;
#pragma unroll
    for (int off = 16; off >= 1; off >>= 1) ss += __shfl_xor_sync(0xffffffffu, ss, off);
    float inv = rsqrtf(ss * (1.0f / HDIM) + EPSV);
    x.x *= inv; x.y *= inv; x.z *= inv; x.w *= inv;
    if (w) {
        float4 wv = *(const float4*)(w + lane * 4);
        x.x *= wv.x; x.y *= wv.y; x.z *= wv.z; x.w *= wv.w;
    }
    if (do_rope) {
        float4 c = *(const float4*)(cs + (size_t)s * HDIM + lane * 4);
        float4 v = *(const float4*)(sn + (size_t)s * HDIM + lane * 4);
        float o0 = x.x * c.x - x.y * v.x;
        float o1 = x.y * c.y + x.x * v.y;
        float o2 = x.z * c.z - x.w * v.z;
        float o3 = x.w * c.w + x.z * v.w;
        x.x = o0; x.y = o1; x.z = o2; x.w = o3;
    }
    *(float4*)p = x;
}

// ================= flash attention (tf32 tensor) =================
// Bq=128 (8 warps x 16 q-rows), Bk=64, HD=128. Q in register fragments.
// Smem: Ks [128hd][72kv] (transposed), Vs [64kv][136d], Ps [64kv][136q].
__global__ __launch_bounds__(256, 1) void attn_tc(
    const float* __restrict__ Q, const float* __restrict__ Kp,
    const float* __restrict__ Vp, float* __restrict__ Out,
    int kv_len, int masked, int addout)
{
    extern __shared__ unsigned sm_u[];
    unsigned* Ks = sm_u;                  // 128*72
    unsigned* Vs = sm_u + 128 * 72;       // 64*136
    unsigned* Ps = Vs + 64 * 136;         // 64*136

    const int tid = threadIdx.x;
    const int l = tid & 31, w = tid >> 5;
    const int g = l >> 2, t = l & 3;
    const int h = blockIdx.y;
    const int q0 = blockIdx.x << 7;
    const int qr = q0 + w * 16 + g;

    // Q fragments (scaled, tf32)
    unsigned qf[16][4];
    {
        const float* qp  = Q + (size_t)qr * D_MODEL + h * HDIM;
        const float* qp8 = qp + (size_t)8 * D_MODEL;
#pragma unroll
        for (int ks = 0; ks < 16; ks++) {
            const int cb = ks * 8 + t;
            qf[ks][0] = f2tf(qp[cb] * QSCALE);
            qf[ks][1] = f2tf(qp8[cb] * QSCALE);
            qf[ks][2] = f2tf(qp[cb + 4] * QSCALE);
            qf[ks][3] = f2tf(qp8[cb + 4] * QSCALE);
        }
    }

    float o[16][4];
#pragma unroll
    for (int nt = 0; nt < 16; nt++)
#pragma unroll
        for (int i = 0; i < 4; i++) o[nt][i] = 0.f;
    float mrow0 = -1e30f, mrow1 = -1e30f;
    float lrow0 = 0.f, lrow1 = 0.f;

    const int ldr = tid & 63;
    const int ldc0 = (tid >> 6) << 5;

    const int kt0 = (masked && q0 >= BLOCK_TOK) ? BLOCK_TOK : 0;
    for (int kt = kt0; kt < kv_len; kt += 64) {
        __syncthreads();
        {
            const float* kg = Kp + (size_t)(kt + ldr) * D_MODEL + h * HDIM + ldc0;
            const float* vg = Vp + (size_t)(kt + ldr) * D_MODEL + h * HDIM + ldc0;
#pragma unroll
            for (int i = 0; i < 8; i++) {
                float4 kk = *(const float4*)(kg + i * 4);
                Ks[(ldc0 + i * 4 + 0) * 72 + ldr] = f2tf(kk.x);
                Ks[(ldc0 + i * 4 + 1) * 72 + ldr] = f2tf(kk.y);
                Ks[(ldc0 + i * 4 + 2) * 72 + ldr] = f2tf(kk.z);
                Ks[(ldc0 + i * 4 + 3) * 72 + ldr] = f2tf(kk.w);
                float4 vv = *(const float4*)(vg + i * 4);
                uint4 pv;
                pv.x = f2tf(vv.x); pv.y = f2tf(vv.y); pv.z = f2tf(vv.z); pv.w = f2tf(vv.w);
                *(uint4*)&Vs[ldr * 136 + ldc0 + i * 4] = pv;
            }
        }
        __syncthreads();

        // S = Q K^T (log2-scaled)
        float s[8][4];
#pragma unroll
        for (int nt = 0; nt < 8; nt++)
#pragma unroll
            for (int i = 0; i < 4; i++) s[nt][i] = 0.f;
#pragma unroll
        for (int ks = 0; ks < 16; ks++) {
            const int kr = ks * 8 + t;
#pragma unroll
            for (int nt = 0; nt < 8; nt++) {
                unsigned b0 = Ks[kr * 72 + nt * 8 + g];
                unsigned b1 = Ks[(kr + 4) * 72 + nt * 8 + g];
                mma8(s[nt], qf[ks], b0, b1);
            }
        }

        // online softmax
        float mx0 = -1e30f, mx1 = -1e30f;
#pragma unroll
        for (int nt = 0; nt < 8; nt++) {
            mx0 = fmaxf(mx0, fmaxf(s[nt][0], s[nt][1]));
            mx1 = fmaxf(mx1, fmaxf(s[nt][2], s[nt][3]));
        }
        mx0 = fmaxf(mx0, __shfl_xor_sync(0xffffffffu, mx0, 1));
        mx0 = fmaxf(mx0, __shfl_xor_sync(0xffffffffu, mx0, 2));
        mx1 = fmaxf(mx1, __shfl_xor_sync(0xffffffffu, mx1, 1));
        mx1 = fmaxf(mx1, __shfl_xor_sync(0xffffffffu, mx1, 2));
        const float mn0 = fmaxf(mrow0, mx0), mn1 = fmaxf(mrow1, mx1);
        const float al0 = exp2f(mrow0 - mn0), al1 = exp2f(mrow1 - mn1);
        mrow0 = mn0; mrow1 = mn1;

        float sum0 = 0.f, sum1 = 0.f;
#pragma unroll
        for (int nt = 0; nt < 8; nt++) {
            float p0 = exp2f(s[nt][0] - mn0);
            float p1 = exp2f(s[nt][1] - mn0);
            float p2 = exp2f(s[nt][2] - mn1);
            float p3 = exp2f(s[nt][3] - mn1);
            sum0 += p0 + p1;
            sum1 += p2 + p3;
            const int nb = nt * 8 + 2 * t;
            Ps[(nb + 0) * 136 + w * 16 + g]     = f2tf(p0);
            Ps[(nb + 1) * 136 + w * 16 + g]     = f2tf(p1);
            Ps[(nb + 0) * 136 + w * 16 + g + 8] = f2tf(p2);
            Ps[(nb + 1) * 136 + w * 16 + g + 8] = f2tf(p3);
        }
        sum0 += __shfl_xor_sync(0xffffffffu, sum0, 1);
        sum0 += __shfl_xor_sync(0xffffffffu, sum0, 2);
        sum1 += __shfl_xor_sync(0xffffffffu, sum1, 1);
        sum1 += __shfl_xor_sync(0xffffffffu, sum1, 2);
        lrow0 = lrow0 * al0 + sum0;
        lrow1 = lrow1 * al1 + sum1;
#pragma unroll
        for (int nt = 0; nt < 16; nt++) {
            o[nt][0] *= al0; o[nt][1] *= al0;
            o[nt][2] *= al1; o[nt][3] *= al1;
        }
        __syncwarp();

        // O += P V
#pragma unroll
        for (int ks = 0; ks < 8; ks++) {
            const int kr = ks * 8 + t;
            unsigned pa[4];
            pa[0] = Ps[kr * 136 + w * 16 + g];
            pa[1] = Ps[kr * 136 + w * 16 + g + 8];
            pa[2] = Ps[(kr + 4) * 136 + w * 16 + g];
            pa[3] = Ps[(kr + 4) * 136 + w * 16 + g + 8];
#pragma unroll
            for (int nt = 0; nt < 16; nt++) {
                unsigned b0 = Vs[kr * 136 + nt * 8 + g];
                unsigned b1 = Vs[(kr + 4) * 136 + nt * 8 + g];
                mma8(o[nt], pa, b0, b1);
            }
        }
    }

    // epilogue
    const float inv0 = 1.f / lrow0, inv1 = 1.f / lrow1;
    float* op0 = Out + (size_t)qr * D_MODEL + h * HDIM;
    float* op1 = op0 + (size_t)8 * D_MODEL;
#pragma unroll
    for (int nt = 0; nt < 16; nt++) {
        const int cc = nt * 8 + 2 * t;
        float2 v0 = make_float2(o[nt][0] * inv0, o[nt][1] * inv0);
        float2 v1 = make_float2(o[nt][2] * inv1, o[nt][3] * inv1);
        if (addout) {
            float2 e0 = *(const float2*)(op0 + cc);
            float2 e1 = *(const float2*)(op1 + cc);
            v0.x += e0.x; v0.y += e0.y; v1.x += e1.x; v1.y += e1.y;
        }
        *(float2*)(op0 + cc) = v0;
        *(float2*)(op1 + cc) = v1;
    }
}

// ---------------- host launcher ----------------
extern "C" void kernel_launch(void* const* d_in, const int* in_sizes, int n_in,
                              void* d_out, int out_size)
{
    (void)in_sizes; (void)n_in; (void)out_size;
    const float* x    = (const float*)d_in[0];
    const float* img  = (const float*)d_in[1];
    const float* cosr = (const float*)d_in[2];
    const float* sinr = (const float*)d_in[3];
    const float* Wq   = (const float*)d_in[4];
    const float* bq   = (const float*)d_in[5];
    const float* Wk   = (const float*)d_in[6];
    const float* bk   = (const float*)d_in[7];
    const float* Wv   = (const float*)d_in[8];
    const float* bv   = (const float*)d_in[9];
    const float* qd   = (const float*)d_in[10];
    const float* qu   = (const float*)d_in[11];
    const float* kd   = (const float*)d_in[12];
    const float* ku   = (const float*)d_in[13];
    const float* vd   = (const float*)d_in[14];
    const float* vu   = (const float*)d_in[15];
    const float* nqw  = (const float*)d_in[16];
    const float* nkw  = (const float*)d_in[17];
    const float* Wkip = (const float*)d_in[18];
    const float* Wvip = (const float*)d_in[19];
    float* out = (float*)d_out;

    float *q, *k, *v, *kip, *vip, *lt;
    cudaGetSymbolAddress((void**)&q,   g_q);
    cudaGetSymbolAddress((void**)&k,   g_k);
    cudaGetSymbolAddress((void**)&v,   g_v);
    cudaGetSymbolAddress((void**)&kip, g_kip);
    cudaGetSymbolAddress((void**)&vip, g_vip);
    cudaGetSymbolAddress((void**)&lt,  g_lt);

    // QKV projections (batched over z)
    {
        Gemm3 P;
        P.A[0] = x;  P.A[1] = x;  P.A[2] = x;
        P.B[0] = Wq; P.B[1] = Wk; P.B[2] = Wv;
        P.bias[0] = bq; P.bias[1] = bk; P.bias[2] = bv;
        P.C[0] = q;  P.C[1] = k;  P.C[2] = v;
        gemm_tc<false><<<dim3(D_MODEL / 128, S_TOK / 128, 3), 128>>>(P, D_MODEL, D_MODEL, D_MODEL, D_MODEL);
    }
    // LoRA down (cond rows only)
    {
        const float* xc = x + (size_t)BLOCK_TOK * D_MODEL;
        Gemm3 P;
        P.A[0] = xc; P.A[1] = xc; P.A[2] = xc;
        P.B[0] = qd; P.B[1] = kd; P.B[2] = vd;
        P.bias[0] = nullptr; P.bias[1] = nullptr; P.bias[2] = nullptr;
        P.C[0] = lt; P.C[1] = lt + CONDN * RANKN; P.C[2] = lt + 2 * CONDN * RANKN;
        gemm_tc<false><<<dim3(1, CONDN / 128, 3), 128>>>(P, D_MODEL, D_MODEL, D_MODEL, RANKN);
    }
    // LoRA up, accumulate into q/k/v cond rows (alpha/rank * lora_w = 1)
    {
        Gemm3 P;
        P.A[0] = lt; P.A[1] = lt + CONDN * RANKN; P.A[2] = lt + 2 * CONDN * RANKN;
        P.B[0] = qu; P.B[1] = ku; P.B[2] = vu;
        P.bias[0] = nullptr; P.bias[1] = nullptr; P.bias[2] = nullptr;
        P.C[0] = q + (size_t)BLOCK_TOK * D_MODEL;
        P.C[1] = k + (size_t)BLOCK_TOK * D_MODEL;
        P.C[2] = v + (size_t)BLOCK_TOK * D_MODEL;
        gemm_tc<true><<<dim3(D_MODEL / 128, CONDN / 128, 3), 128>>>(P, RANKN, RANKN, RANKN, D_MODEL);
    }
    // RMSNorm + RoPE on q, k
    {
        int nw = S_TOK * NHEAD;
        norm_rope_kernel<<<(nw * 32 + 255) / 256, 256>>>(q, nqw, cosr, sinr, S_TOK, 1);
        norm_rope_kernel<<<(nw * 32 + 255) / 256, 256>>>(k, nkw, cosr, sinr, S_TOK, 1);
    }
    // IP projections
    {
        Gemm3 P;
        P.A[0] = img;  P.A[1] = img;  P.A[2] = img;
        P.B[0] = Wkip; P.B[1] = Wvip; P.B[2] = Wkip;
        P.bias[0] = nullptr; P.bias[1] = nullptr; P.bias[2] = nullptr;
        P.C[0] = kip; P.C[1] = vip; P.C[2] = kip;
        gemm_tc<false><<<dim3(D_MODEL / 128, T_IPN / 128, 2), 128>>>(P, D_IPN, D_IPN, D_IPN, D_MODEL);
    }
    // RMSNorm (no weight, no rope) on k_ip
    {
        int nwip = T_IPN * NHEAD;
        norm_rope_kernel<<<(nwip * 32 + 255) / 256, 256>>>(kip, nullptr, nullptr, nullptr, T_IPN, 0);
    }
    // Attention
    {
        size_t smem = (size_t)(128 * 72 + 64 * 136 + 64 * 136) * 4;  // 106496 B
        cudaFuncSetAttribute(attn_tc, cudaFuncAttributeMaxDynamicSharedMemorySize, (int)smem);
        attn_tc<<<dim3(S_TOK / 128, NHEAD), 256, smem>>>(q, k, v, out, S_TOK, 1, 0);
        attn_tc<<<dim3(S_TOK / 128, NHEAD), 256, smem>>>(q, kip, vip, out, T_IPN, 0, 1);
    }
}

// round 4
// speedup vs baseline: 1.2794x; 1.2794x over previous
#include <cuda_runtime.h>

#define S_TOK     2304
#define D_MODEL   3072
#define NHEAD     24
#define HDIM      128
#define BLOCK_TOK 2048
#define CONDN     256
#define RANKN     128
#define T_IPN     128
#define D_IPN     4096
#define EPSV      1e-5f
// (1/sqrt(128)) * log2(e): softmax computed in exp2 domain
#define QSCALE    0.1275173e+0f

__device__ float g_q[S_TOK * D_MODEL];
__device__ float g_k[S_TOK * D_MODEL];
__device__ float g_v[S_TOK * D_MODEL];
__device__ float g_kip[T_IPN * D_MODEL];
__device__ float g_vip[T_IPN * D_MODEL];
__device__ float g_lt[3 * CONDN * RANKN];

__device__ __forceinline__ unsigned f2tf(float f) {
    unsigned u;
    asm("cvt.rna.tf32.f32 %0, %1;" : "=r"(u) : "f"(f));
    return u;
}
__device__ __forceinline__ void mma8(float* c, const unsigned* a, unsigned b0, unsigned b1) {
    asm volatile(
        "mma.sync.aligned.m16n8k8.row.col.f32.tf32.tf32.f32 "
        "{%0,%1,%2,%3}, {%4,%5,%6,%7}, {%8,%9}, {%0,%1,%2,%3};"
        : "+f"(c[0]), "+f"(c[1]), "+f"(c[2]), "+f"(c[3])
        : "r"(a[0]), "r"(a[1]), "r"(a[2]), "r"(a[3]), "r"(b0), "r"(b1));
}
__device__ __forceinline__ void cpa16(unsigned dst, const void* src) {
    asm volatile("cp.async.cg.shared.global [%0], [%1], 16;" :: "r"(dst), "l"(src));
}
__device__ __forceinline__ void cp_commit() { asm volatile("cp.async.commit_group;"); }
__device__ __forceinline__ void cp_wait0() { asm volatile("cp.async.wait_group 0;"); }

// ============ batched GEMM: C[M,N] (+)= A[M,K] @ B[N,K]^T + bias ============
// 128x128 tile, BK=16, 128 thr (4 warps, 64x64 warp tile), cp.async double buffer.
// Smem [mn][k] stride 20 (conflict-free), tf32 cvt at fragment load.
struct GemmB {
    const float* A[8]; const float* Bm[8]; const float* bias[8]; float* C[8];
    int M[8], N[8], K[8];
};

template <bool ACC>
__global__ __launch_bounds__(128, 2) void gemm_tc(GemmB P)
{
    __shared__ float As[2][2560];
    __shared__ float Bs[2][2560];
    const int z = blockIdx.z;
    const int M = P.M[z], N = P.N[z], K = P.K[z];
    const int bm = blockIdx.y << 7, bn = blockIdx.x << 7;
    if (bm >= M || bn >= N) return;
    const float* A = P.A[z];
    const float* Bw = P.Bm[z];
    const float* bias = P.bias[z];
    float* C = P.C[z];

    const int tid = threadIdx.x;
    const int lw = tid & 31, w = tid >> 5, g = lw >> 2, t = lw & 3;
    const int wm = w & 1, wn = w >> 1;

    const float* Arow = A + (size_t)(bm + tid) * K;
    const float* Brow = Bw + (size_t)(bn + tid) * K;
    const unsigned as_u = (unsigned)__cvta_generic_to_shared(As) + tid * 80;
    const unsigned bs_u = (unsigned)__cvta_generic_to_shared(Bs) + tid * 80;

    float acc[4][8][4];
#pragma unroll
    for (int mt = 0; mt < 4; mt++)
#pragma unroll
        for (int nt = 0; nt < 8; nt++)
#pragma unroll
            for (int i = 0; i < 4; i++) acc[mt][nt][i] = 0.f;

    // preload tile 0
#pragma unroll
    for (int c = 0; c < 4; c++) {
        cpa16(as_u + c * 16, Arow + c * 4);
        cpa16(bs_u + c * 16, Brow + c * 4);
    }
    cp_commit();

    const int niter = K >> 4;
    for (int it = 0; it < niter; it++) {
        const int cur = it & 1;
        cp_wait0();
        __syncthreads();
        if (it + 1 < niter) {
            const int k0 = (it + 1) << 4;
            const unsigned off = (unsigned)((cur ^ 1) * 2560 * 4);
#pragma unroll
            for (int c = 0; c < 4; c++) {
                cpa16(as_u + off + c * 16, Arow + k0 + c * 4);
                cpa16(bs_u + off + c * 16, Brow + k0 + c * 4);
            }
            cp_commit();
        }
#pragma unroll
        for (int ks = 0; ks < 2; ks++) {
            const int kr = ks * 8 + t;
            unsigned af[4][4], bf[8][2];
#pragma unroll
            for (int mt = 0; mt < 4; mt++) {
                const float* ap = &As[cur][(wm * 64 + mt * 16 + g) * 20 + kr];
                af[mt][0] = f2tf(ap[0]);
                af[mt][1] = f2tf(ap[160]);
                af[mt][2] = f2tf(ap[4]);
                af[mt][3] = f2tf(ap[164]);
            }
#pragma unroll
            for (int nt = 0; nt < 8; nt++) {
                const float* bp = &Bs[cur][(wn * 64 + nt * 8 + g) * 20 + kr];
                bf[nt][0] = f2tf(bp[0]);
                bf[nt][1] = f2tf(bp[4]);
            }
#pragma unroll
            for (int mt = 0; mt < 4; mt++)
#pragma unroll
                for (int nt = 0; nt < 8; nt++)
                    mma8(acc[mt][nt], af[mt], bf[nt][0], bf[nt][1]);
        }
        __syncthreads();
    }

#pragma unroll
    for (int mt = 0; mt < 4; mt++) {
        const int r0 = bm + wm * 64 + mt * 16 + g;
        const int r1 = r0 + 8;
#pragma unroll
        for (int nt = 0; nt < 8; nt++) {
            const int cc = bn + wn * 64 + nt * 8 + 2 * t;
            float2 v0 = make_float2(acc[mt][nt][0], acc[mt][nt][1]);
            float2 v1 = make_float2(acc[mt][nt][2], acc[mt][nt][3]);
            if (bias) {
                float bx = bias[cc], by = bias[cc + 1];
                v0.x += bx; v0.y += by; v1.x += bx; v1.y += by;
            }
            float* p0 = C + (size_t)r0 * N + cc;
            float* p1 = C + (size_t)r1 * N + cc;
            if (ACC) {
                float2 e0 = *(const float2*)p0, e1 = *(const float2*)p1;
                v0.x += e0.x; v0.y += e0.y; v1.x += e1.x; v1.y += e1.y;
            }
            *(float2*)p0 = v0;
            *(float2*)p1 = v1;
        }
    }
}

// ---------------- fused rmsnorm (+weight)(+rope): y=0 q, y=1 k, y=2 k_ip ----------------
__global__ void norm_all_kernel(float* q, float* k, float* kip,
                                const float* wq, const float* wk,
                                const float* cs, const float* sn)
{
    const int y = blockIdx.y;
    float* tp = (y == 0) ? q : (y == 1) ? k : kip;
    const float* wp = (y == 0) ? wq : (y == 1) ? wk : nullptr;
    const int rows = (y == 2) ? T_IPN : S_TOK;
    const int do_rope = (y != 2);
    int gwarp = (blockIdx.x * blockDim.x + threadIdx.x) >> 5;
    int lane = threadIdx.x & 31;
    if (gwarp >= rows * NHEAD) return;
    int s = gwarp / NHEAD, h = gwarp % NHEAD;
    float* p = tp + (size_t)s * D_MODEL + h * HDIM + lane * 4;
    float4 x = *(const float4*)p;
    float ss = x.x * x.x + x.y * x.y + x.z * x.z + x.w * x.w;
#pragma unroll
    for (int off = 16; off >= 1; off >>= 1) ss += __shfl_xor_sync(0xffffffffu, ss, off);
    float inv = rsqrtf(ss * (1.0f / HDIM) + EPSV);
    x.x *= inv; x.y *= inv; x.z *= inv; x.w *= inv;
    if (wp) {
        float4 wv = *(const float4*)(wp + lane * 4);
        x.x *= wv.x; x.y *= wv.y; x.z *= wv.z; x.w *= wv.w;
    }
    if (do_rope) {
        float4 c = *(const float4*)(cs + (size_t)s * HDIM + lane * 4);
        float4 v = *(const float4*)(sn + (size_t)s * HDIM + lane * 4);
        float o0 = x.x * c.x - x.y * v.x;
        float o1 = x.y * c.y + x.x * v.y;
        float o2 = x.z * c.z - x.w * v.z;
        float o3 = x.w * c.w + x.z * v.w;
        x.x = o0; x.y = o1; x.z = o2; x.w = o3;
    }
    *(float4*)p = x;
}

// ============ flash attention (tf32), cp.async double-buffered K/V ============
// Bq=128 (8 warps x 16 q), Bk=64, HD=128. Q in registers. K,V natural [kv][d].
// Smem: Ks [2][64][132], Vs [2][64][136], Ps [64][136]. 168 KB.
__global__ __launch_bounds__(256, 1) void attn_tc(
    const float* __restrict__ Q, const float* __restrict__ Kp,
    const float* __restrict__ Vp, float* __restrict__ Out,
    int kv_len, int masked, int addout)
{
    extern __shared__ float smf[];
    float* Ks = smf;                        // 2 * 64*132
    float* Vs = smf + 2 * 8448;             // 2 * 64*136
    unsigned* Ps = (unsigned*)(smf + 2 * 8448 + 2 * 8704);  // 64*136

    const int tid = threadIdx.x;
    const int l = tid & 31, w = tid >> 5;
    const int g = l >> 2, t = l & 3;
    const int h = blockIdx.y;
    const int q0 = blockIdx.x << 7;
    const int qr = q0 + w * 16 + g;

    unsigned qf[16][4];
    {
        const float* qp = Q + (size_t)qr * D_MODEL + h * HDIM;
        const float* qp8 = qp + (size_t)8 * D_MODEL;
#pragma unroll
        for (int ks = 0; ks < 16; ks++) {
            const int cb = ks * 8 + t;
            qf[ks][0] = f2tf(qp[cb] * QSCALE);
            qf[ks][1] = f2tf(qp8[cb] * QSCALE);
            qf[ks][2] = f2tf(qp[cb + 4] * QSCALE);
            qf[ks][3] = f2tf(qp8[cb + 4] * QSCALE);
        }
    }

    float o[16][4];
#pragma unroll
    for (int nt = 0; nt < 16; nt++)
#pragma unroll
        for (int i = 0; i < 4; i++) o[nt][i] = 0.f;
    float mrow0 = -1e30f, mrow1 = -1e30f, lrow0 = 0.f, lrow1 = 0.f;

    const int row = tid >> 2, seg = (tid & 3) * 32;
    const unsigned ks_u = (unsigned)__cvta_generic_to_shared(Ks) + (row * 132 + seg) * 4;
    const unsigned vs_u = (unsigned)__cvta_generic_to_shared(Vs) + (row * 136 + seg) * 4;

    const int kt0 = (masked && q0 >= BLOCK_TOK) ? BLOCK_TOK : 0;
    const int ntiles = (kv_len - kt0) >> 6;

    // preload tile 0
    {
        const float* kg = Kp + (size_t)(kt0 + row) * D_MODEL + h * HDIM + seg;
        const float* vg = Vp + (size_t)(kt0 + row) * D_MODEL + h * HDIM + seg;
#pragma unroll
        for (int c = 0; c < 8; c++) {
            cpa16(ks_u + c * 16, kg + c * 4);
            cpa16(vs_u + c * 16, vg + c * 4);
        }
        cp_commit();
    }

    for (int it = 0; it < ntiles; it++) {
        const int cur = it & 1;
        cp_wait0();
        __syncthreads();
        if (it + 1 < ntiles) {
            const int kt = kt0 + (it + 1) * 64;
            const float* kg = Kp + (size_t)(kt + row) * D_MODEL + h * HDIM + seg;
            const float* vg = Vp + (size_t)(kt + row) * D_MODEL + h * HDIM + seg;
            const unsigned ko = ks_u + (cur ^ 1) * 8448 * 4;
            const unsigned vo = vs_u + (cur ^ 1) * 8704 * 4;
#pragma unroll
            for (int c = 0; c < 8; c++) {
                cpa16(ko + c * 16, kg + c * 4);
                cpa16(vo + c * 16, vg + c * 4);
            }
            cp_commit();
        }
        const float* Kc = Ks + cur * 8448;
        const float* Vc = Vs + cur * 8704;

        // S = Q K^T (exp2 domain)
        float s[8][4];
#pragma unroll
        for (int nt = 0; nt < 8; nt++)
#pragma unroll
            for (int i = 0; i < 4; i++) s[nt][i] = 0.f;
#pragma unroll
        for (int ks = 0; ks < 16; ks++) {
            const int kr = ks * 8 + t;
#pragma unroll
            for (int nt = 0; nt < 8; nt++) {
                const float* kp2 = Kc + (nt * 8 + g) * 132 + kr;
                mma8(s[nt], qf[ks], f2tf(kp2[0]), f2tf(kp2[4]));
            }
        }

        // online softmax (rows r0 = w*16+g, r1 = r0+8)
        float mx0 = -1e30f, mx1 = -1e30f;
#pragma unroll
        for (int nt = 0; nt < 8; nt++) {
            mx0 = fmaxf(mx0, fmaxf(s[nt][0], s[nt][1]));
            mx1 = fmaxf(mx1, fmaxf(s[nt][2], s[nt][3]));
        }
        mx0 = fmaxf(mx0, __shfl_xor_sync(0xffffffffu, mx0, 1));
        mx0 = fmaxf(mx0, __shfl_xor_sync(0xffffffffu, mx0, 2));
        mx1 = fmaxf(mx1, __shfl_xor_sync(0xffffffffu, mx1, 1));
        mx1 = fmaxf(mx1, __shfl_xor_sync(0xffffffffu, mx1, 2));
        const float mn0 = fmaxf(mrow0, mx0), mn1 = fmaxf(mrow1, mx1);
        const float al0 = exp2f(mrow0 - mn0), al1 = exp2f(mrow1 - mn1);
        mrow0 = mn0; mrow1 = mn1;

        float sum0 = 0.f, sum1 = 0.f;
#pragma unroll
        for (int nt = 0; nt < 8; nt++) {
            float p0 = exp2f(s[nt][0] - mn0);
            float p1 = exp2f(s[nt][1] - mn0);
            float p2 = exp2f(s[nt][2] - mn1);
            float p3 = exp2f(s[nt][3] - mn1);
            sum0 += p0 + p1;
            sum1 += p2 + p3;
            const int nb = nt * 8 + 2 * t;
            Ps[(nb + 0) * 136 + w * 16 + g]     = f2tf(p0);
            Ps[(nb + 1) * 136 + w * 16 + g]     = f2tf(p1);
            Ps[(nb + 0) * 136 + w * 16 + g + 8] = f2tf(p2);
            Ps[(nb + 1) * 136 + w * 16 + g + 8] = f2tf(p3);
        }
        sum0 += __shfl_xor_sync(0xffffffffu, sum0, 1);
        sum0 += __shfl_xor_sync(0xffffffffu, sum0, 2);
        sum1 += __shfl_xor_sync(0xffffffffu, sum1, 1);
        sum1 += __shfl_xor_sync(0xffffffffu, sum1, 2);
        lrow0 = lrow0 * al0 + sum0;
        lrow1 = lrow1 * al1 + sum1;
#pragma unroll
        for (int nt = 0; nt < 16; nt++) {
            o[nt][0] *= al0; o[nt][1] *= al0;
            o[nt][2] *= al1; o[nt][3] *= al1;
        }
        __syncwarp();

        // O += P V
#pragma unroll
        for (int ks = 0; ks < 8; ks++) {
            const int kr = ks * 8 + t;
            unsigned pa[4];
            pa[0] = Ps[kr * 136 + w * 16 + g];
            pa[1] = Ps[kr * 136 + w * 16 + g + 8];
            pa[2] = Ps[(kr + 4) * 136 + w * 16 + g];
            pa[3] = Ps[(kr + 4) * 136 + w * 16 + g + 8];
#pragma unroll
            for (int nt = 0; nt < 16; nt++) {
                const float* vp2 = Vc + kr * 136 + nt * 8 + g;
                mma8(o[nt], pa, f2tf(vp2[0]), f2tf(vp2[4 * 136]));
            }
        }
    }

    const float inv0 = 1.f / lrow0, inv1 = 1.f / lrow1;
    float* op0 = Out + (size_t)qr * D_MODEL + h * HDIM;
    float* op1 = op0 + (size_t)8 * D_MODEL;
#pragma unroll
    for (int nt = 0; nt < 16; nt++) {
        const int cc = nt * 8 + 2 * t;
        float2 v0 = make_float2(o[nt][0] * inv0, o[nt][1] * inv0);
        float2 v1 = make_float2(o[nt][2] * inv1, o[nt][3] * inv1);
        if (addout) {
            float2 e0 = *(const float2*)(op0 + cc);
            float2 e1 = *(const float2*)(op1 + cc);
            v0.x += e0.x; v0.y += e0.y; v1.x += e1.x; v1.y += e1.y;
        }
        *(float2*)(op0 + cc) = v0;
        *(float2*)(op1 + cc) = v1;
    }
}

// ---------------- host launcher ----------------
extern "C" void kernel_launch(void* const* d_in, const int* in_sizes, int n_in,
                              void* d_out, int out_size)
{
    (void)in_sizes; (void)n_in; (void)out_size;
    const float* x    = (const float*)d_in[0];
    const float* img  = (const float*)d_in[1];
    const float* cosr = (const float*)d_in[2];
    const float* sinr = (const float*)d_in[3];
    const float* Wq   = (const float*)d_in[4];
    const float* bq   = (const float*)d_in[5];
    const float* Wk   = (const float*)d_in[6];
    const float* bk   = (const float*)d_in[7];
    const float* Wv   = (const float*)d_in[8];
    const float* bv   = (const float*)d_in[9];
    const float* qd   = (const float*)d_in[10];
    const float* qu   = (const float*)d_in[11];
    const float* kd   = (const float*)d_in[12];
    const float* ku   = (const float*)d_in[13];
    const float* vd   = (const float*)d_in[14];
    const float* vu   = (const float*)d_in[15];
    const float* nqw  = (const float*)d_in[16];
    const float* nkw  = (const float*)d_in[17];
    const float* Wkip = (const float*)d_in[18];
    const float* Wvip = (const float*)d_in[19];
    float* out = (float*)d_out;

    float *q, *k, *v, *kip, *vip, *lt;
    cudaGetSymbolAddress((void**)&q,   g_q);
    cudaGetSymbolAddress((void**)&k,   g_k);
    cudaGetSymbolAddress((void**)&v,   g_v);
    cudaGetSymbolAddress((void**)&kip, g_kip);
    cudaGetSymbolAddress((void**)&vip, g_vip);
    cudaGetSymbolAddress((void**)&lt,  g_lt);

    const float* xc = x + (size_t)BLOCK_TOK * D_MODEL;

    // mega GEMM: z 0-2 QKV, z 3-5 LoRA-down, z 6-7 IP projections
    {
        GemmB P;
        P.A[0] = x;  P.A[1] = x;  P.A[2] = x;
        P.Bm[0] = Wq; P.Bm[1] = Wk; P.Bm[2] = Wv;
        P.bias[0] = bq; P.bias[1] = bk; P.bias[2] = bv;
        P.C[0] = q;  P.C[1] = k;  P.C[2] = v;
        P.M[0] = P.M[1] = P.M[2] = S_TOK;
        P.N[0] = P.N[1] = P.N[2] = D_MODEL;
        P.K[0] = P.K[1] = P.K[2] = D_MODEL;
        P.A[3] = xc; P.A[4] = xc; P.A[5] = xc;
        P.Bm[3] = qd; P.Bm[4] = kd; P.Bm[5] = vd;
        P.bias[3] = P.bias[4] = P.bias[5] = nullptr;
        P.C[3] = lt; P.C[4] = lt + CONDN * RANKN; P.C[5] = lt + 2 * CONDN * RANKN;
        P.M[3] = P.M[4] = P.M[5] = CONDN;
        P.N[3] = P.N[4] = P.N[5] = RANKN;
        P.K[3] = P.K[4] = P.K[5] = D_MODEL;
        P.A[6] = img; P.A[7] = img;
        P.Bm[6] = Wkip; P.Bm[7] = Wvip;
        P.bias[6] = P.bias[7] = nullptr;
        P.C[6] = kip; P.C[7] = vip;
        P.M[6] = P.M[7] = T_IPN;
        P.N[6] = P.N[7] = D_MODEL;
        P.K[6] = P.K[7] = D_IPN;
        gemm_tc<false><<<dim3(D_MODEL / 128, S_TOK / 128, 8), 128>>>(P);
    }
    // LoRA up: accumulate into q/k/v cond rows (alpha/rank * lora_w = 1)
    {
        GemmB P;
        P.A[0] = lt; P.A[1] = lt + CONDN * RANKN; P.A[2] = lt + 2 * CONDN * RANKN;
        P.Bm[0] = qu; P.Bm[1] = ku; P.Bm[2] = vu;
        P.bias[0] = P.bias[1] = P.bias[2] = nullptr;
        P.C[0] = q + (size_t)BLOCK_TOK * D_MODEL;
        P.C[1] = k + (size_t)BLOCK_TOK * D_MODEL;
        P.C[2] = v + (size_t)BLOCK_TOK * D_MODEL;
        for (int i = 0; i < 3; i++) { P.M[i] = CONDN; P.N[i] = D_MODEL; P.K[i] = RANKN; }
        for (int i = 3; i < 8; i++) { P.A[i] = nullptr; P.Bm[i] = nullptr; P.bias[i] = nullptr; P.C[i] = nullptr; P.M[i] = 0; P.N[i] = 0; P.K[i] = 16; }
        gemm_tc<true><<<dim3(D_MODEL / 128, CONDN / 128, 3), 128>>>(P);
    }
    // fused norms: q, k (rope) + kip
    norm_all_kernel<<<dim3((S_TOK * NHEAD * 32 + 255) / 256, 3), 256>>>(q, k, kip, nqw, nkw, cosr, sinr);
    // attention
    {
        size_t smem = (size_t)(2 * 8448 + 2 * 8704 + 64 * 136) * 4;  // 172032 B
        cudaFuncSetAttribute(attn_tc, cudaFuncAttributeMaxDynamicSharedMemorySize, (int)smem);
        attn_tc<<<dim3(S_TOK / 128, NHEAD), 256, smem>>>(q, k, v, out, S_TOK, 1, 0);
        attn_tc<<<dim3(S_TOK / 128, NHEAD), 256, smem>>>(q, kip, vip, out, T_IPN, 0, 1);
    }
}

// round 5
// speedup vs baseline: 1.5332x; 1.1984x over previous
#include <cuda_runtime.h>

#define S_TOK     2304
#define D_MODEL   3072
#define NHEAD     24
#define HDIM      128
#define BLOCK_TOK 2048
#define CONDN     256
#define RANKN     128
#define T_IPN     128
#define D_IPN     4096
#define EPSV      1e-5f
// (1/sqrt(128)) * log2(e): softmax computed in exp2 domain
#define QSCALE    0.1275173e+0f

__device__ float g_q[S_TOK * D_MODEL];
__device__ float g_k[S_TOK * D_MODEL];
__device__ float g_v[S_TOK * D_MODEL];
__device__ float g_kip[T_IPN * D_MODEL];
__device__ float g_vip[T_IPN * D_MODEL];
__device__ float g_lt[3 * CONDN * RANKN];

__device__ __forceinline__ unsigned f2tf(float f) {
    unsigned u;
    asm("cvt.rna.tf32.f32 %0, %1;" : "=r"(u) : "f"(f));
    return u;
}
__device__ __forceinline__ void mma8(float* c, const unsigned* a, unsigned b0, unsigned b1) {
    asm volatile(
        "mma.sync.aligned.m16n8k8.row.col.f32.tf32.tf32.f32 "
        "{%0,%1,%2,%3}, {%4,%5,%6,%7}, {%8,%9}, {%0,%1,%2,%3};"
        : "+f"(c[0]), "+f"(c[1]), "+f"(c[2]), "+f"(c[3])
        : "r"(a[0]), "r"(a[1]), "r"(a[2]), "r"(a[3]), "r"(b0), "r"(b1));
}
__device__ __forceinline__ void cpa16(unsigned dst, const void* src) {
    asm volatile("cp.async.cg.shared.global [%0], [%1], 16;" :: "r"(dst), "l"(src));
}
__device__ __forceinline__ void cp_commit() { asm volatile("cp.async.commit_group;"); }
__device__ __forceinline__ void cp_wait0() { asm volatile("cp.async.wait_group 0;"); }

// ============ batched GEMM: C[M,N] (+)= A[M,K] @ B[N,K]^T + bias ============
// 128x128 tile, BK=16, 256 thr (8 warps, 64x32 warp tile), <=128 regs -> 2 CTA/SM.
struct GemmB {
    const float* A[8]; const float* Bm[8]; const float* bias[8]; float* C[8];
    int M[8], N[8], K[8];
};

template <bool ACC>
__global__ __launch_bounds__(256, 2) void gemm_tc(GemmB P)
{
    __shared__ float As[2][2560];
    __shared__ float Bs[2][2560];
    const int z = blockIdx.z;
    const int M = P.M[z], N = P.N[z], K = P.K[z];
    const int bm = blockIdx.y << 7, bn = blockIdx.x << 7;
    if (bm >= M || bn >= N) return;
    const float* A = P.A[z];
    const float* Bw = P.Bm[z];
    const float* bias = P.bias[z];
    float* C = P.C[z];

    const int tid = threadIdx.x;
    const int lw = tid & 31, w = tid >> 5, g = lw >> 2, t = lw & 3;
    const int wm = w & 1, wn = w >> 1;   // 2 x 4 warp grid, warp tile 64x32

    const int lrow = tid >> 1, lseg = (tid & 1) * 8;
    const float* Arow = A + (size_t)(bm + lrow) * K + lseg;
    const float* Brow = Bw + (size_t)(bn + lrow) * K + lseg;
    const unsigned as_u = (unsigned)__cvta_generic_to_shared(As) + (lrow * 20 + lseg) * 4;
    const unsigned bs_u = (unsigned)__cvta_generic_to_shared(Bs) + (lrow * 20 + lseg) * 4;

    float acc[4][4][4];
#pragma unroll
    for (int mt = 0; mt < 4; mt++)
#pragma unroll
        for (int nt = 0; nt < 4; nt++)
#pragma unroll
            for (int i = 0; i < 4; i++) acc[mt][nt][i] = 0.f;

    // preload tile 0
    cpa16(as_u, Arow);        cpa16(as_u + 16, Arow + 4);
    cpa16(bs_u, Brow);        cpa16(bs_u + 16, Brow + 4);
    cp_commit();

    const int niter = K >> 4;
    for (int it = 0; it < niter; it++) {
        const int cur = it & 1;
        cp_wait0();
        __syncthreads();
        if (it + 1 < niter) {
            const int k0 = (it + 1) << 4;
            const unsigned off = (unsigned)((cur ^ 1) * 2560 * 4);
            cpa16(as_u + off, Arow + k0);      cpa16(as_u + off + 16, Arow + k0 + 4);
            cpa16(bs_u + off, Brow + k0);      cpa16(bs_u + off + 16, Brow + k0 + 4);
            cp_commit();
        }
#pragma unroll
        for (int ks = 0; ks < 2; ks++) {
            const int kr = ks * 8 + t;
            unsigned af[4][4], bf[4][2];
#pragma unroll
            for (int mt = 0; mt < 4; mt++) {
                const float* ap = &As[cur][(wm * 64 + mt * 16 + g) * 20 + kr];
                af[mt][0] = f2tf(ap[0]);
                af[mt][1] = f2tf(ap[160]);
                af[mt][2] = f2tf(ap[4]);
                af[mt][3] = f2tf(ap[164]);
            }
#pragma unroll
            for (int nt = 0; nt < 4; nt++) {
                const float* bp = &Bs[cur][(wn * 32 + nt * 8 + g) * 20 + kr];
                bf[nt][0] = f2tf(bp[0]);
                bf[nt][1] = f2tf(bp[4]);
            }
#pragma unroll
            for (int mt = 0; mt < 4; mt++)
#pragma unroll
                for (int nt = 0; nt < 4; nt++)
                    mma8(acc[mt][nt], af[mt], bf[nt][0], bf[nt][1]);
        }
        __syncthreads();
    }

#pragma unroll
    for (int mt = 0; mt < 4; mt++) {
        const int r0 = bm + wm * 64 + mt * 16 + g;
        const int r1 = r0 + 8;
#pragma unroll
        for (int nt = 0; nt < 4; nt++) {
            const int cc = bn + wn * 32 + nt * 8 + 2 * t;
            float2 v0 = make_float2(acc[mt][nt][0], acc[mt][nt][1]);
            float2 v1 = make_float2(acc[mt][nt][2], acc[mt][nt][3]);
            if (bias) {
                float bx = bias[cc], by = bias[cc + 1];
                v0.x += bx; v0.y += by; v1.x += bx; v1.y += by;
            }
            float* p0 = C + (size_t)r0 * N + cc;
            float* p1 = C + (size_t)r1 * N + cc;
            if (ACC) {
                float2 e0 = *(const float2*)p0, e1 = *(const float2*)p1;
                v0.x += e0.x; v0.y += e0.y; v1.x += e1.x; v1.y += e1.y;
            }
            *(float2*)p0 = v0;
            *(float2*)p1 = v1;
        }
    }
}

// ------- fused norm/round: y=0 q(norm+rope+w, *QSCALE) 1=k(norm+rope+w) 2=kip(norm)
//         3=v(round) 4=vip(round). All outputs stored tf32-rounded (rna). -------
__global__ void norm_all_kernel(float* q, float* k, float* kip, float* v, float* vip,
                                const float* wq, const float* wk,
                                const float* cs, const float* sn)
{
    const int y = blockIdx.y;
    float* tp; const float* wp = nullptr;
    int rows = S_TOK, mode = 2;  // 0 norm+rope, 1 norm, 2 round-only
    float sc = 1.f;
    if (y == 0)      { tp = q;   wp = wq; mode = 0; sc = QSCALE; }
    else if (y == 1) { tp = k;   wp = wk; mode = 0; }
    else if (y == 2) { tp = kip; rows = T_IPN; mode = 1; }
    else if (y == 3) { tp = v; }
    else             { tp = vip; rows = T_IPN; }

    int gwarp = (blockIdx.x * blockDim.x + threadIdx.x) >> 5;
    int lane = threadIdx.x & 31;
    if (gwarp >= rows * NHEAD) return;
    int s = gwarp / NHEAD, h = gwarp % NHEAD;
    float* p = tp + (size_t)s * D_MODEL + h * HDIM + lane * 4;
    float4 x = *(const float4*)p;
    if (mode <= 1) {
        float ss = x.x * x.x + x.y * x.y + x.z * x.z + x.w * x.w;
#pragma unroll
        for (int off = 16; off >= 1; off >>= 1) ss += __shfl_xor_sync(0xffffffffu, ss, off);
        float inv = rsqrtf(ss * (1.0f / HDIM) + EPSV);
        x.x *= inv; x.y *= inv; x.z *= inv; x.w *= inv;
        if (wp) {
            float4 wv = *(const float4*)(wp + lane * 4);
            x.x *= wv.x; x.y *= wv.y; x.z *= wv.z; x.w *= wv.w;
        }
        if (mode == 0) {
            float4 c = *(const float4*)(cs + (size_t)s * HDIM + lane * 4);
            float4 v2 = *(const float4*)(sn + (size_t)s * HDIM + lane * 4);
            float o0 = x.x * c.x - x.y * v2.x;
            float o1 = x.y * c.y + x.x * v2.y;
            float o2 = x.z * c.z - x.w * v2.z;
            float o3 = x.w * c.w + x.z * v2.w;
            x.x = o0; x.y = o1; x.z = o2; x.w = o3;
        }
    }
    x.x = __uint_as_float(f2tf(x.x * sc));
    x.y = __uint_as_float(f2tf(x.y * sc));
    x.z = __uint_as_float(f2tf(x.z * sc));
    x.w = __uint_as_float(f2tf(x.w * sc));
    *(float4*)p = x;
}

// ============ fused flash attention (tf32, pre-rounded operands) ============
// Bq=128 (8 warps x 16 q), Bk=64, HD=128. Phase 0: main (block-masked) writes Out;
// Phase 1: IP (kv=128) RMW-adds into Out. Q fragments live across both phases.
__global__ __launch_bounds__(256, 1) void attn_tc(
    const unsigned* __restrict__ Q, const unsigned* __restrict__ Km,
    const unsigned* __restrict__ Vm, const unsigned* __restrict__ Ki,
    const unsigned* __restrict__ Vi, float* __restrict__ Out)
{
    extern __shared__ unsigned smu[];
    unsigned* Ks = smu;                     // 2 * 64*132
    unsigned* Vs = smu + 2 * 8448;          // 2 * 64*136
    unsigned* Ps = Vs + 2 * 8704;           // 64*136

    const int tid = threadIdx.x;
    const int l = tid & 31, w = tid >> 5;
    const int g = l >> 2, t = l & 3;
    const int h = blockIdx.y;
    const int q0 = blockIdx.x << 7;
    const int qr = q0 + w * 16 + g;

    unsigned qf[16][4];
    {
        const unsigned* qp = Q + (size_t)qr * D_MODEL + h * HDIM;
        const unsigned* qp8 = qp + (size_t)8 * D_MODEL;
#pragma unroll
        for (int ks = 0; ks < 16; ks++) {
            const int cb = ks * 8 + t;
            qf[ks][0] = qp[cb];
            qf[ks][1] = qp8[cb];
            qf[ks][2] = qp[cb + 4];
            qf[ks][3] = qp8[cb + 4];
        }
    }

    const int row = tid >> 2, seg = (tid & 3) * 32;
    const unsigned ks_u = (unsigned)__cvta_generic_to_shared(Ks) + (row * 132 + seg) * 4;
    const unsigned vs_u = (unsigned)__cvta_generic_to_shared(Vs) + (row * 136 + seg) * 4;
    float* op0 = Out + (size_t)qr * D_MODEL + h * HDIM;
    float* op1 = op0 + (size_t)8 * D_MODEL;

#pragma unroll 1
    for (int ph = 0; ph < 2; ph++) {
        const unsigned* Kb = ph ? Ki : Km;
        const unsigned* Vb = ph ? Vi : Vm;
        const int kt0 = (ph == 0 && q0 >= BLOCK_TOK) ? BLOCK_TOK : 0;
        const int ntiles = ((ph ? T_IPN : S_TOK) - kt0) >> 6;

        float o[16][4];
#pragma unroll
        for (int nt = 0; nt < 16; nt++)
#pragma unroll
            for (int i = 0; i < 4; i++) o[nt][i] = 0.f;
        float mrow0 = -1e30f, mrow1 = -1e30f, lrow0 = 0.f, lrow1 = 0.f;

        __syncthreads();   // smem free from previous phase
        {
            const unsigned* kg = Kb + (size_t)(kt0 + row) * D_MODEL + h * HDIM + seg;
            const unsigned* vg = Vb + (size_t)(kt0 + row) * D_MODEL + h * HDIM + seg;
#pragma unroll
            for (int c = 0; c < 8; c++) {
                cpa16(ks_u + c * 16, kg + c * 4);
                cpa16(vs_u + c * 16, vg + c * 4);
            }
            cp_commit();
        }

        for (int it = 0; it < ntiles; it++) {
            const int cur = it & 1;
            cp_wait0();
            __syncthreads();
            if (it + 1 < ntiles) {
                const int kt = kt0 + (it + 1) * 64;
                const unsigned* kg = Kb + (size_t)(kt + row) * D_MODEL + h * HDIM + seg;
                const unsigned* vg = Vb + (size_t)(kt + row) * D_MODEL + h * HDIM + seg;
                const unsigned ko = ks_u + (cur ^ 1) * 8448 * 4;
                const unsigned vo = vs_u + (cur ^ 1) * 8704 * 4;
#pragma unroll
                for (int c = 0; c < 8; c++) {
                    cpa16(ko + c * 16, kg + c * 4);
                    cpa16(vo + c * 16, vg + c * 4);
                }
                cp_commit();
            }
            const unsigned* Kc = Ks + cur * 8448;
            const unsigned* Vc = Vs + cur * 8704;

            // S = Q K^T (exp2 domain)
            float s[8][4];
#pragma unroll
            for (int nt = 0; nt < 8; nt++)
#pragma unroll
                for (int i = 0; i < 4; i++) s[nt][i] = 0.f;
#pragma unroll
            for (int ks = 0; ks < 16; ks++) {
                const int kr = ks * 8 + t;
#pragma unroll
                for (int nt = 0; nt < 8; nt++) {
                    const unsigned* kp2 = Kc + (nt * 8 + g) * 132 + kr;
                    mma8(s[nt], qf[ks], kp2[0], kp2[4]);
                }
            }

            // online softmax (rows r0 = w*16+g, r1 = r0+8)
            float mx0 = -1e30f, mx1 = -1e30f;
#pragma unroll
            for (int nt = 0; nt < 8; nt++) {
                mx0 = fmaxf(mx0, fmaxf(s[nt][0], s[nt][1]));
                mx1 = fmaxf(mx1, fmaxf(s[nt][2], s[nt][3]));
            }
            mx0 = fmaxf(mx0, __shfl_xor_sync(0xffffffffu, mx0, 1));
            mx0 = fmaxf(mx0, __shfl_xor_sync(0xffffffffu, mx0, 2));
            mx1 = fmaxf(mx1, __shfl_xor_sync(0xffffffffu, mx1, 1));
            mx1 = fmaxf(mx1, __shfl_xor_sync(0xffffffffu, mx1, 2));
            const float mn0 = fmaxf(mrow0, mx0), mn1 = fmaxf(mrow1, mx1);
            const float al0 = exp2f(mrow0 - mn0), al1 = exp2f(mrow1 - mn1);
            mrow0 = mn0; mrow1 = mn1;

            float sum0 = 0.f, sum1 = 0.f;
#pragma unroll
            for (int nt = 0; nt < 8; nt++) {
                float p0 = exp2f(s[nt][0] - mn0);
                float p1 = exp2f(s[nt][1] - mn0);
                float p2 = exp2f(s[nt][2] - mn1);
                float p3 = exp2f(s[nt][3] - mn1);
                sum0 += p0 + p1;
                sum1 += p2 + p3;
                const int nb = nt * 8 + 2 * t;
                Ps[(nb + 0) * 136 + w * 16 + g]     = f2tf(p0);
                Ps[(nb + 1) * 136 + w * 16 + g]     = f2tf(p1);
                Ps[(nb + 0) * 136 + w * 16 + g + 8] = f2tf(p2);
                Ps[(nb + 1) * 136 + w * 16 + g + 8] = f2tf(p3);
            }
            sum0 += __shfl_xor_sync(0xffffffffu, sum0, 1);
            sum0 += __shfl_xor_sync(0xffffffffu, sum0, 2);
            sum1 += __shfl_xor_sync(0xffffffffu, sum1, 1);
            sum1 += __shfl_xor_sync(0xffffffffu, sum1, 2);
            lrow0 = lrow0 * al0 + sum0;
            lrow1 = lrow1 * al1 + sum1;
#pragma unroll
            for (int nt = 0; nt < 16; nt++) {
                o[nt][0] *= al0; o[nt][1] *= al0;
                o[nt][2] *= al1; o[nt][3] *= al1;
            }
            __syncwarp();

            // O += P V
#pragma unroll
            for (int ks = 0; ks < 8; ks++) {
                const int kr = ks * 8 + t;
                unsigned pa[4];
                pa[0] = Ps[kr * 136 + w * 16 + g];
                pa[1] = Ps[kr * 136 + w * 16 + g + 8];
                pa[2] = Ps[(kr + 4) * 136 + w * 16 + g];
                pa[3] = Ps[(kr + 4) * 136 + w * 16 + g + 8];
#pragma unroll
                for (int nt = 0; nt < 16; nt++) {
                    const unsigned* vp2 = Vc + kr * 136 + nt * 8 + g;
                    mma8(o[nt], pa, vp2[0], vp2[4 * 136]);
                }
            }
        }

        const float inv0 = 1.f / lrow0, inv1 = 1.f / lrow1;
#pragma unroll
        for (int nt = 0; nt < 16; nt++) {
            const int cc = nt * 8 + 2 * t;
            float2 v0 = make_float2(o[nt][0] * inv0, o[nt][1] * inv0);
            float2 v1 = make_float2(o[nt][2] * inv1, o[nt][3] * inv1);
            if (ph == 1) {
                float2 e0 = *(const float2*)(op0 + cc);
                float2 e1 = *(const float2*)(op1 + cc);
                v0.x += e0.x; v0.y += e0.y; v1.x += e1.x; v1.y += e1.y;
            }
            *(float2*)(op0 + cc) = v0;
            *(float2*)(op1 + cc) = v1;
        }
    }
}

// ---------------- host launcher ----------------
extern "C" void kernel_launch(void* const* d_in, const int* in_sizes, int n_in,
                              void* d_out, int out_size)
{
    (void)in_sizes; (void)n_in; (void)out_size;
    const float* x    = (const float*)d_in[0];
    const float* img  = (const float*)d_in[1];
    const float* cosr = (const float*)d_in[2];
    const float* sinr = (const float*)d_in[3];
    const float* Wq   = (const float*)d_in[4];
    const float* bq   = (const float*)d_in[5];
    const float* Wk   = (const float*)d_in[6];
    const float* bk   = (const float*)d_in[7];
    const float* Wv   = (const float*)d_in[8];
    const float* bv   = (const float*)d_in[9];
    const float* qd   = (const float*)d_in[10];
    const float* qu   = (const float*)d_in[11];
    const float* kd   = (const float*)d_in[12];
    const float* ku   = (const float*)d_in[13];
    const float* vd   = (const float*)d_in[14];
    const float* vu   = (const float*)d_in[15];
    const float* nqw  = (const float*)d_in[16];
    const float* nkw  = (const float*)d_in[17];
    const float* Wkip = (const float*)d_in[18];
    const float* Wvip = (const float*)d_in[19];
    float* out = (float*)d_out;

    float *q, *k, *v, *kip, *vip, *lt;
    cudaGetSymbolAddress((void**)&q,   g_q);
    cudaGetSymbolAddress((void**)&k,   g_k);
    cudaGetSymbolAddress((void**)&v,   g_v);
    cudaGetSymbolAddress((void**)&kip, g_kip);
    cudaGetSymbolAddress((void**)&vip, g_vip);
    cudaGetSymbolAddress((void**)&lt,  g_lt);

    const float* xc = x + (size_t)BLOCK_TOK * D_MODEL;

    // mega GEMM: z 0-2 QKV, z 3-5 LoRA-down, z 6-7 IP projections
    {
        GemmB P;
        P.A[0] = x;  P.A[1] = x;  P.A[2] = x;
        P.Bm[0] = Wq; P.Bm[1] = Wk; P.Bm[2] = Wv;
        P.bias[0] = bq; P.bias[1] = bk; P.bias[2] = bv;
        P.C[0] = q;  P.C[1] = k;  P.C[2] = v;
        P.M[0] = P.M[1] = P.M[2] = S_TOK;
        P.N[0] = P.N[1] = P.N[2] = D_MODEL;
        P.K[0] = P.K[1] = P.K[2] = D_MODEL;
        P.A[3] = xc; P.A[4] = xc; P.A[5] = xc;
        P.Bm[3] = qd; P.Bm[4] = kd; P.Bm[5] = vd;
        P.bias[3] = P.bias[4] = P.bias[5] = nullptr;
        P.C[3] = lt; P.C[4] = lt + CONDN * RANKN; P.C[5] = lt + 2 * CONDN * RANKN;
        P.M[3] = P.M[4] = P.M[5] = CONDN;
        P.N[3] = P.N[4] = P.N[5] = RANKN;
        P.K[3] = P.K[4] = P.K[5] = D_MODEL;
        P.A[6] = img; P.A[7] = img;
        P.Bm[6] = Wkip; P.Bm[7] = Wvip;
        P.bias[6] = P.bias[7] = nullptr;
        P.C[6] = kip; P.C[7] = vip;
        P.M[6] = P.M[7] = T_IPN;
        P.N[6] = P.N[7] = D_MODEL;
        P.K[6] = P.K[7] = D_IPN;
        gemm_tc<false><<<dim3(D_MODEL / 128, S_TOK / 128, 8), 256>>>(P);
    }
    // LoRA up: accumulate into q/k/v cond rows (alpha/rank * lora_w = 1)
    {
        GemmB P;
        P.A[0] = lt; P.A[1] = lt + CONDN * RANKN; P.A[2] = lt + 2 * CONDN * RANKN;
        P.Bm[0] = qu; P.Bm[1] = ku; P.Bm[2] = vu;
        P.bias[0] = P.bias[1] = P.bias[2] = nullptr;
        P.C[0] = q + (size_t)BLOCK_TOK * D_MODEL;
        P.C[1] = k + (size_t)BLOCK_TOK * D_MODEL;
        P.C[2] = v + (size_t)BLOCK_TOK * D_MODEL;
        for (int i = 0; i < 3; i++) { P.M[i] = CONDN; P.N[i] = D_MODEL; P.K[i] = RANKN; }
        for (int i = 3; i < 8; i++) { P.A[i] = nullptr; P.Bm[i] = nullptr; P.bias[i] = nullptr; P.C[i] = nullptr; P.M[i] = 0; P.N[i] = 0; P.K[i] = 16; }
        gemm_tc<true><<<dim3(D_MODEL / 128, CONDN / 128, 3), 256>>>(P);
    }
    // fused norms + tf32 pre-rounding: q(+QSCALE), k, kip, v, vip
    norm_all_kernel<<<dim3((S_TOK * NHEAD * 32 + 255) / 256, 5), 256>>>(q, k, kip, v, vip, nqw, nkw, cosr, sinr);
    // fused attention: main (masked) + IP phase
    {
        size_t smem = (size_t)(2 * 8448 + 2 * 8704 + 64 * 136) * 4;  // 172032 B
        cudaFuncSetAttribute(attn_tc, cudaFuncAttributeMaxDynamicSharedMemorySize, (int)smem);
        attn_tc<<<dim3(S_TOK / 128, NHEAD), 256, smem>>>(
            (const unsigned*)q, (const unsigned*)k, (const unsigned*)v,
            (const unsigned*)kip, (const unsigned*)vip, out);
    }
}